// round 10
// baseline (speedup 1.0000x reference)
#include <cuda_runtime.h>
#include <math.h>

// MultiConvPerm, fused single kernel, hybrid store path:
//   - middle 768 floats of each 1024-row are zeros -> cp.async.bulk (3KB/row)
//     from a shared 3KB zero buffer (same source for every row)
//   - head/tail 128-float edge segments -> STG.128 from per-warp smem acc
//   - coef[12] lives in shared (register relief -> 8 blocks/SM occupancy)
//
// out[co,ci,:] (W=1024) is zero except:
//   out[x] = acc[28-x]    for x in [0,28]
//   out[x] = acc[1052-x]  for x in [996,1023]
// acc[t] = sum over static (wi,j) with t = p_wi + d_wi*j of coef[wi]*w_wi[row,j]
// coef   = softmax(alpha + gumbels)   (log_softmax shift cancels)

#define NW 12
#define NROWS 65536            // CO*CI = 256*256
#define WARPS_PER_BLOCK 8
#define ROWS_PER_WARP 4
#define ZERO_FLOATS 768        // middle floats per row, 3072 bytes

struct WPtrs {
    const float* w[NW];
};

// compile-time tap geometry (KD = product((3,5,7,9),(1,3,7)), S=57)
__device__ __forceinline__ void tap_params(int wi, int& k, int& d, int& p) {
    const int ks[NW] = {3,3,3, 5,5,5, 7,7,7, 9,9,9};
    const int ds[NW] = {1,3,7, 1,3,7, 1,3,7, 1,3,7};
    const int ps[NW] = {27,25,21, 26,22,14, 25,19,7, 24,16,0};
    k = ks[wi]; d = ds[wi]; p = ps[wi];
}

__device__ __forceinline__ unsigned int smem_u32(const void* p) {
    return (unsigned int)__cvta_generic_to_shared(p);
}

template<bool FAST1024>
__global__ __launch_bounds__(WARPS_PER_BLOCK * 32, 8)
void multiconv_kernel(WPtrs wp, const float* __restrict__ alpha,
                      const float* __restrict__ gumbels,
                      float* __restrict__ out, int W) {
    __shared__ __align__(16) float s_zero[ZERO_FLOATS];
    __shared__ float s_acc[WARPS_PER_BLOCK][ROWS_PER_WARP][64];
    __shared__ float s_coef[NW];

    const int tid = threadIdx.x;
    const int warp = tid >> 5;
    const int lane = tid & 31;

    const int row0 = (blockIdx.x * WARPS_PER_BLOCK + warp) * ROWS_PER_WARP;

    // ---- init shared zero buffer + coef (once per block) -------------------
    if (FAST1024 && tid < ZERO_FLOATS / 4) {
        reinterpret_cast<float4*>(s_zero)[tid] = make_float4(0.f, 0.f, 0.f, 0.f);
    }
    if (tid < NW) {
        // each of threads 0..11 redundantly computes the softmax, writes one slot
        float v[NW];
        float m = -1e30f;
        #pragma unroll
        for (int i = 0; i < NW; i++) {
            v[i] = alpha[i] + gumbels[i];
            m = fmaxf(m, v[i]);
        }
        float s = 0.0f;
        #pragma unroll
        for (int i = 0; i < NW; i++) {
            v[i] = __expf(v[i] - m);
            s += v[i];
        }
        s_coef[tid] = v[tid] * __fdividef(1.0f, s);
    }
    if (FAST1024) {
        // make generic-proxy smem writes visible to the async (bulk-copy) proxy
        asm volatile("fence.proxy.async.shared::cta;" ::: "memory");
    }
    __syncthreads();

    // ---- phase A: one 3KB bulk zero-store per row, deep async queue --------
    if (FAST1024 && lane == 0) {
        const unsigned int src = smem_u32(s_zero);
        #pragma unroll
        for (int r = 0; r < ROWS_PER_WARP; r++) {
            float* dst = out + (size_t)(row0 + r) * 1024 + 128;
            asm volatile(
                "cp.async.bulk.global.shared::cta.bulk_group [%0], [%1], %2;"
                :: "l"(dst), "r"(src), "r"(ZERO_FLOATS * 4) : "memory");
        }
        asm volatile("cp.async.bulk.commit_group;" ::: "memory");
    }

    // ---- phase B: per-lane accumulators over static taps -------------------
    // lane owns t0 = lane and t1 = lane+32 (valid while t1 <= 56)
    float f0[ROWS_PER_WARP], f1[ROWS_PER_WARP];
    #pragma unroll
    for (int r = 0; r < ROWS_PER_WARP; r++) { f0[r] = 0.0f; f1[r] = 0.0f; }

    const bool hasHi = (lane < 25);

    #pragma unroll
    for (int wi = 0; wi < NW; wi++) {
        int k, d, p;
        tap_params(wi, k, d, p);

        const int u0 = lane - p;
        const int u1 = lane + 32 - p;
        const bool v0 = (u0 >= 0) && (u0 % d == 0) && (u0 / d < k);
        const bool v1 = hasHi && (u1 >= 0) && (u1 % d == 0) && (u1 / d < k);
        const int j0 = u0 / d;
        const int j1 = u1 / d;

        const float c = s_coef[wi];   // LDS broadcast
        const float* base = wp.w[wi] + (size_t)row0 * k;
        #pragma unroll
        for (int r = 0; r < ROWS_PER_WARP; r++) {
            if (v0) f0[r] += c * base[r * k + j0];
            if (v1) f1[r] += c * base[r * k + j1];
        }
    }

    #pragma unroll
    for (int r = 0; r < ROWS_PER_WARP; r++) {
        s_acc[warp][r][lane] = f0[r];
        if (hasHi) s_acc[warp][r][lane + 32] = f1[r];
    }
    __syncwarp();

    // ---- phase C: edge stores (STG.128 from smem acc) ----------------------
    if (FAST1024) {
        #pragma unroll
        for (int r = 0; r < ROWS_PER_WARP; r++) {
            const float* A = s_acc[warp][r];
            float* orow = out + (size_t)(row0 + r) * 1024;
            // head: x in [0,128), nonzero for x <= 28
            {
                const int x = lane * 4;
                float4 v;
                v.x = (x + 0 < 29) ? A[28 - (x + 0)] : 0.0f;
                v.y = (x + 1 < 29) ? A[28 - (x + 1)] : 0.0f;
                v.z = (x + 2 < 29) ? A[28 - (x + 2)] : 0.0f;
                v.w = (x + 3 < 29) ? A[28 - (x + 3)] : 0.0f;
                *reinterpret_cast<float4*>(orow + x) = v;
            }
            // tail: x in [896,1024), nonzero for x >= 996
            {
                const int x = 896 + lane * 4;
                float4 v;
                v.x = (x + 0 >= 996) ? A[1052 - (x + 0)] : 0.0f;
                v.y = (x + 1 >= 996) ? A[1052 - (x + 1)] : 0.0f;
                v.z = (x + 2 >= 996) ? A[1052 - (x + 2)] : 0.0f;
                v.w = (x + 3 >= 996) ? A[1052 - (x + 3)] : 0.0f;
                *reinterpret_cast<float4*>(orow + x) = v;
            }
        }
        // drain this warp's bulk-store group before block exit
        if (lane == 0) {
            asm volatile("cp.async.bulk.wait_group 0;" ::: "memory");
        }
    } else {
        const int lo = 29, hi = W - 28;
        #pragma unroll
        for (int r = 0; r < ROWS_PER_WARP; r++) {
            const float* A = s_acc[warp][r];
            float* orow = out + (size_t)(row0 + r) * (size_t)W;
            for (int x0 = lane * 4; x0 < W; x0 += 128) {
                float4 v;
                #pragma unroll
                for (int q = 0; q < 4; q++) {
                    const int x = x0 + q;
                    float f = 0.0f;
                    if (x < lo) f = A[28 - x];
                    else if (x >= hi) f = A[W + 28 - x];
                    (&v.x)[q] = f;
                }
                *reinterpret_cast<float4*>(orow + x0) = v;
            }
        }
    }
}

extern "C" void kernel_launch(void* const* d_in, const int* in_sizes, int n_in,
                              void* d_out, int out_size) {
    WPtrs wp;
    for (int i = 0; i < NW; i++) wp.w[i] = (const float*)d_in[i];
    const float* alpha = (const float*)d_in[12];
    const float* gumbels = (const float*)d_in[13];
    float* out = (float*)d_out;

    const int W = out_size / NROWS;  // spatial size (1024)
    const int rows_per_block = WARPS_PER_BLOCK * ROWS_PER_WARP;
    const int grid = (NROWS + rows_per_block - 1) / rows_per_block;

    if (W == 1024) {
        multiconv_kernel<true><<<grid, WARPS_PER_BLOCK * 32>>>(wp, alpha, gumbels, out, W);
    } else {
        multiconv_kernel<false><<<grid, WARPS_PER_BLOCK * 32>>>(wp, alpha, gumbels, out, W);
    }
}